// round 1
// baseline (speedup 1.0000x reference)
#include <cuda_runtime.h>
#include <math.h>

#define T_SEQ  2048
#define NFEAT  8192
#define NH     4
#define DV     256
#define HALF_N 4096   // NFEAT/2

// ---- device scratch (allocation-free rule: __device__ globals) ----
__device__ float  g_QR[(size_t)NH * T_SEQ * NFEAT];        // 268 MB
__device__ float  g_S [(size_t)NH * T_SEQ * T_SEQ];        // 67 MB (lower-tri tiles only valid)
__device__ float2 g_tab[(size_t)T_SEQ * HALF_N];           // 67 MB cos/sin table

// ============================================================================
// Kernel 1: cos/sin table.  freq(p) = 2^(-p/256) / (2*pi), phase = t*freq,
// ang = frac(phase)*2*pi.  fp64 phase => exact mod-1; cospif/sinpif for the
// final trig (exact pi-argument reduction).
// ============================================================================
__global__ void build_tab_kernel() {
    int i = blockIdx.x * 256 + threadIdx.x;
    if (i >= T_SEQ * HALF_N) return;
    int t = i >> 12;              // HALF_N = 4096 = 2^12
    int p = i & (HALF_N - 1);
    double freq  = exp2(-(double)p * (1.0 / 256.0)) * (1.0 / (2.0 * M_PI));
    double phase = (double)t * freq;
    double fr    = phase - floor(phase);
    float  x     = (float)(2.0 * fr);      // cos(2*pi*fr) = cospi(2*fr)
    g_tab[i] = make_float2(cospif(x), sinpif(x));
}

// ============================================================================
// Kernel 2: apply RoPE to Q -> g_QR.  Pairs (even,odd) share one (cos,sin).
// ============================================================================
__global__ void rope_kernel(const float* __restrict__ Q) {
    size_t i = (size_t)blockIdx.x * 256 + threadIdx.x;   // pair index
    if (i >= (size_t)NH * T_SEQ * HALF_N) return;
    size_t r = i & ((size_t)T_SEQ * HALF_N - 1);         // head stride is 2^23
    float2 q  = ((const float2*)Q)[i];
    float2 cs = g_tab[r];
    float2 o;
    o.x = q.x * cs.x - q.y * cs.y;   // v_even*cos + (-v_odd)*sin
    o.y = q.y * cs.x + q.x * cs.y;   // v_odd *cos + ( v_even)*sin
    ((float2*)g_QR)[i] = o;
}

// ============================================================================
// Kernel 3: S = tril(QR * QR^T, k=-1) per head.  Only lower-tri 128x128 tiles
// are computed (136 of 256); diagonal tiles masked strictly-lower.
// BM=BN=128, BK=8, 256 threads, 8x8 microtile, double-buffered smem.
// ============================================================================
__global__ __launch_bounds__(256, 2) void gemm_scores_kernel() {
    const int h = blockIdx.y;
    const float* __restrict__ Ah = g_QR + (size_t)h * T_SEQ * NFEAT;
    float* __restrict__ Sh = g_S + (size_t)h * T_SEQ * T_SEQ;

    // decode lower-triangular tile index: lt = bi*(bi+1)/2 + bj, bj <= bi
    int lt = blockIdx.x;
    int bi = (int)((sqrtf(8.0f * (float)lt + 1.0f) - 1.0f) * 0.5f);
    while ((bi + 1) * (bi + 2) / 2 <= lt) ++bi;
    while (bi * (bi + 1) / 2 > lt)        --bi;
    int bj = lt - bi * (bi + 1) / 2;

    __shared__ float As[2][8][132];   // [k][m], padded
    __shared__ float Bs[2][8][132];   // [k][n]

    const int tid  = threadIdx.x;
    const int lrow = tid >> 1;          // 0..127
    const int c4   = (tid & 1) * 4;     // 0 or 4
    const float* ga = Ah + (size_t)(bi * 128 + lrow) * NFEAT + c4;
    const float* gb = Ah + (size_t)(bj * 128 + lrow) * NFEAT + c4;

    const int tx = tid & 15, ty = tid >> 4;

    float acc[8][8];
#pragma unroll
    for (int i = 0; i < 8; ++i)
#pragma unroll
        for (int j = 0; j < 8; ++j) acc[i][j] = 0.0f;

    // prologue: chunk 0
    {
        float4 ra = *(const float4*)ga;
        float4 rb = *(const float4*)gb;
        As[0][c4 + 0][lrow] = ra.x; As[0][c4 + 1][lrow] = ra.y;
        As[0][c4 + 2][lrow] = ra.z; As[0][c4 + 3][lrow] = ra.w;
        Bs[0][c4 + 0][lrow] = rb.x; Bs[0][c4 + 1][lrow] = rb.y;
        Bs[0][c4 + 2][lrow] = rb.z; Bs[0][c4 + 3][lrow] = rb.w;
    }
    __syncthreads();

    const int NK = NFEAT / 8;   // 1024
    int buf = 0;
    for (int kc = 0; kc < NK; ++kc) {
        float4 na, nb;
        if (kc + 1 < NK) {
            na = *(const float4*)(ga + (size_t)(kc + 1) * 8);
            nb = *(const float4*)(gb + (size_t)(kc + 1) * 8);
        }
#pragma unroll
        for (int k = 0; k < 8; ++k) {
            float4 a0 = *(const float4*)&As[buf][k][ty * 8];
            float4 a1 = *(const float4*)&As[buf][k][ty * 8 + 4];
            float4 b0 = *(const float4*)&Bs[buf][k][tx * 8];
            float4 b1 = *(const float4*)&Bs[buf][k][tx * 8 + 4];
            float a[8] = {a0.x, a0.y, a0.z, a0.w, a1.x, a1.y, a1.z, a1.w};
            float b[8] = {b0.x, b0.y, b0.z, b0.w, b1.x, b1.y, b1.z, b1.w};
#pragma unroll
            for (int i = 0; i < 8; ++i)
#pragma unroll
                for (int j = 0; j < 8; ++j)
                    acc[i][j] = fmaf(a[i], b[j], acc[i][j]);
        }
        if (kc + 1 < NK) {
            int nb2 = buf ^ 1;
            As[nb2][c4 + 0][lrow] = na.x; As[nb2][c4 + 1][lrow] = na.y;
            As[nb2][c4 + 2][lrow] = na.z; As[nb2][c4 + 3][lrow] = na.w;
            Bs[nb2][c4 + 0][lrow] = nb.x; Bs[nb2][c4 + 1][lrow] = nb.y;
            Bs[nb2][c4 + 2][lrow] = nb.z; Bs[nb2][c4 + 3][lrow] = nb.w;
        }
        __syncthreads();
        buf ^= 1;
    }

    // writeback (strictly-lower mask on diagonal tiles)
    const int row0 = bi * 128 + ty * 8;
    const int col0 = bj * 128 + tx * 8;
    const bool diag = (bi == bj);
#pragma unroll
    for (int i = 0; i < 8; ++i) {
        float* dst = Sh + (size_t)(row0 + i) * T_SEQ + col0;
        if (!diag) {
            *(float4*)(dst)     = make_float4(acc[i][0], acc[i][1], acc[i][2], acc[i][3]);
            *(float4*)(dst + 4) = make_float4(acc[i][4], acc[i][5], acc[i][6], acc[i][7]);
        } else {
#pragma unroll
            for (int j = 0; j < 8; ++j)
                dst[j] = (col0 + j < row0 + i) ? acc[i][j] : 0.0f;
        }
    }
}

// ============================================================================
// Kernel 4: out = S * V per head, reading only valid tiles (kt <= bi).
// Same tiling.  V is shared across heads.
// ============================================================================
__global__ __launch_bounds__(256, 2) void gemm_out_kernel(const float* __restrict__ V,
                                                          float* __restrict__ O) {
    const int h  = blockIdx.z;
    const int bi = blockIdx.y;   // row tile 0..15
    const int bj = blockIdx.x;   // col tile 0..1 (DV=256)
    const float* __restrict__ Sh = g_S + (size_t)h * T_SEQ * T_SEQ;
    float* __restrict__ Oh = O + (size_t)h * T_SEQ * DV;

    __shared__ float As[2][8][132];   // S tile, [k][m]
    __shared__ float Bs[2][8][132];   // V tile, [k][n]

    const int tid  = threadIdx.x;
    const int lrow = tid >> 1;
    const int c4   = (tid & 1) * 4;
    const float* ga = Sh + (size_t)(bi * 128 + lrow) * T_SEQ + c4;

    const int vrow = tid >> 5;            // 0..7
    const int vcol = (tid & 31) * 4;      // 0..124
    const float* gv = V + (size_t)vrow * DV + bj * 128 + vcol;

    const int tx = tid & 15, ty = tid >> 4;

    float acc[8][8];
#pragma unroll
    for (int i = 0; i < 8; ++i)
#pragma unroll
        for (int j = 0; j < 8; ++j) acc[i][j] = 0.0f;

    {
        float4 ra = *(const float4*)ga;
        float4 rv = *(const float4*)gv;
        As[0][c4 + 0][lrow] = ra.x; As[0][c4 + 1][lrow] = ra.y;
        As[0][c4 + 2][lrow] = ra.z; As[0][c4 + 3][lrow] = ra.w;
        *(float4*)&Bs[0][vrow][vcol] = rv;
    }
    __syncthreads();

    const int NK = (bi + 1) * 16;   // K-chunks of 8 covering s-tiles 0..bi
    int buf = 0;
    for (int kc = 0; kc < NK; ++kc) {
        float4 na, nv;
        if (kc + 1 < NK) {
            na = *(const float4*)(ga + (size_t)(kc + 1) * 8);
            nv = *(const float4*)(gv + (size_t)(kc + 1) * 8 * DV);
        }
#pragma unroll
        for (int k = 0; k < 8; ++k) {
            float4 a0 = *(const float4*)&As[buf][k][ty * 8];
            float4 a1 = *(const float4*)&As[buf][k][ty * 8 + 4];
            float4 b0 = *(const float4*)&Bs[buf][k][tx * 8];
            float4 b1 = *(const float4*)&Bs[buf][k][tx * 8 + 4];
            float a[8] = {a0.x, a0.y, a0.z, a0.w, a1.x, a1.y, a1.z, a1.w};
            float b[8] = {b0.x, b0.y, b0.z, b0.w, b1.x, b1.y, b1.z, b1.w};
#pragma unroll
            for (int i = 0; i < 8; ++i)
#pragma unroll
                for (int j = 0; j < 8; ++j)
                    acc[i][j] = fmaf(a[i], b[j], acc[i][j]);
        }
        if (kc + 1 < NK) {
            int nb2 = buf ^ 1;
            As[nb2][c4 + 0][lrow] = na.x; As[nb2][c4 + 1][lrow] = na.y;
            As[nb2][c4 + 2][lrow] = na.z; As[nb2][c4 + 3][lrow] = na.w;
            *(float4*)&Bs[nb2][vrow][vcol] = nv;
        }
        __syncthreads();
        buf ^= 1;
    }

    const int row0 = bi * 128 + ty * 8;
    const int col0 = bj * 128 + tx * 8;
#pragma unroll
    for (int i = 0; i < 8; ++i) {
        float* dst = Oh + (size_t)(row0 + i) * DV + col0;
        *(float4*)(dst)     = make_float4(acc[i][0], acc[i][1], acc[i][2], acc[i][3]);
        *(float4*)(dst + 4) = make_float4(acc[i][4], acc[i][5], acc[i][6], acc[i][7]);
    }
}

// ============================================================================
extern "C" void kernel_launch(void* const* d_in, const int* in_sizes, int n_in,
                              void* d_out, int out_size) {
    const float* Q = (const float*)d_in[0];   // (1,4,2048,8192) f32
    const float* V = (const float*)d_in[1];   // (1,1,2048,256)  f32
    float* O = (float*)d_out;                 // (1,4,2048,256)  f32

    const int tab_elems  = T_SEQ * HALF_N;                 // 8,388,608
    const int rope_pairs = NH * T_SEQ * HALF_N;            // 33,554,432

    build_tab_kernel<<<(tab_elems + 255) / 256, 256>>>();
    rope_kernel<<<(rope_pairs + 255) / 256, 256>>>(Q);
    gemm_scores_kernel<<<dim3(136, NH), 256>>>();          // 136 lower-tri tiles/head
    gemm_out_kernel<<<dim3(DV / 128, T_SEQ / 128, NH), 256>>>(V, O);
}

// round 3
// speedup vs baseline: 2.3113x; 2.3113x over previous
#include <cuda_runtime.h>
#include <cuda_bf16.h>
#include <math.h>

#define T_SEQ  2048
#define NFEAT  8192
#define NH     4
#define DV     256
#define HALF_N 4096   // NFEAT/2

// ---- device scratch (allocation-free rule: __device__ globals) ----
__device__ __nv_bfloat16 g_Qhi[(size_t)NH * T_SEQ * NFEAT];   // 134 MB
__device__ __nv_bfloat16 g_Qlo[(size_t)NH * T_SEQ * NFEAT];   // 134 MB
__device__ float         g_S [(size_t)NH * T_SEQ * T_SEQ];    // 67 MB
__device__ float2        g_tab[(size_t)T_SEQ * HALF_N];       // 67 MB cos/sin
__device__ double        g_freq[HALF_N];

// ============================================================================
// Kernel 0: per-pair frequency (fp64 exp2 hoisted out of the big table pass)
// ============================================================================
__global__ void freq_kernel() {
    int p = blockIdx.x * 256 + threadIdx.x;
    if (p >= HALF_N) return;
    g_freq[p] = exp2(-(double)p * (1.0 / 256.0)) * (1.0 / (2.0 * M_PI));
}

// ============================================================================
// Kernel 1: cos/sin table. fp64 phase => exact mod-1; cospif/sinpif.
// ============================================================================
__global__ void build_tab_kernel() {
    int i = blockIdx.x * 256 + threadIdx.x;
    if (i >= T_SEQ * HALF_N) return;
    int t = i >> 12;              // HALF_N = 4096 = 2^12
    int p = i & (HALF_N - 1);
    double phase = (double)t * g_freq[p];
    double fr    = phase - floor(phase);
    float  x     = (float)(2.0 * fr);      // cos(2*pi*fr) = cospi(2*fr)
    g_tab[i] = make_float2(cospif(x), sinpif(x));
}

// ============================================================================
// Kernel 2: RoPE -> split bf16 (hi + lo), lo = residual after bf16 rounding.
// ============================================================================
__global__ void rope_kernel(const float* __restrict__ Q) {
    size_t i = (size_t)blockIdx.x * 256 + threadIdx.x;   // pair index
    if (i >= (size_t)NH * T_SEQ * HALF_N) return;
    size_t r = i & ((size_t)T_SEQ * HALF_N - 1);         // head stride is 2^23
    float2 q  = ((const float2*)Q)[i];
    float2 cs = g_tab[r];
    float ox = q.x * cs.x - q.y * cs.y;
    float oy = q.y * cs.x + q.x * cs.y;
    __nv_bfloat16 hx = __float2bfloat16(ox);
    __nv_bfloat16 hy = __float2bfloat16(oy);
    float lx = ox - __bfloat162float(hx);
    float ly = oy - __bfloat162float(hy);
    __nv_bfloat162 h; h.x = hx; h.y = hy;
    __nv_bfloat162 l; l.x = __float2bfloat16(lx); l.y = __float2bfloat16(ly);
    ((__nv_bfloat162*)g_Qhi)[i] = h;
    ((__nv_bfloat162*)g_Qlo)[i] = l;
}

// ============================================================================
// Kernel 3: S = tril(QR*QR^T, k=-1) via split-bf16 HMMA (3 passes: hh, h*lo, lo*h).
// Tile 128x128, BK=32, 256 threads (8 warps: 2m x 4n, each 64x32).
// smem rows padded to 40 bf16 (80B) -> conflict-free ldmatrix.
// ============================================================================
#define BK        32
#define LDS_PAD   40                       // bf16 elems per row in smem
#define ARR_BYTES (128 * LDS_PAD * 2)      // 10240
#define BUF_BYTES (4 * ARR_BYTES)          // 40960 (Ahi, Alo, Bhi, Blo)
#define SMEM_BYTES (2 * BUF_BYTES)         // 81920

#define OFF_AHI 0
#define OFF_ALO (1 * ARR_BYTES)
#define OFF_BHI (2 * ARR_BYTES)
#define OFF_BLO (3 * ARR_BYTES)

__device__ __forceinline__ void ldsm4(unsigned& r0, unsigned& r1, unsigned& r2, unsigned& r3,
                                      unsigned addr) {
    asm volatile("ldmatrix.sync.aligned.m8n8.x4.shared.b16 {%0,%1,%2,%3}, [%4];"
                 : "=r"(r0), "=r"(r1), "=r"(r2), "=r"(r3) : "r"(addr));
}

__device__ __forceinline__ void mma_bf16(float* c, const unsigned* a, const unsigned* b) {
    asm volatile("mma.sync.aligned.m16n8k16.row.col.f32.bf16.bf16.f32 "
                 "{%0,%1,%2,%3}, {%4,%5,%6,%7}, {%8,%9}, {%0,%1,%2,%3};"
                 : "+f"(c[0]), "+f"(c[1]), "+f"(c[2]), "+f"(c[3])
                 : "r"(a[0]), "r"(a[1]), "r"(a[2]), "r"(a[3]), "r"(b[0]), "r"(b[1]));
}

__global__ __launch_bounds__(256, 1) void gemm_scores_kernel() {
    extern __shared__ char smem[];
    const unsigned smem_u32 = (unsigned)__cvta_generic_to_shared(smem);

    const int h = blockIdx.y;
    const __nv_bfloat16* __restrict__ Qhi = g_Qhi + (size_t)h * T_SEQ * NFEAT;
    const __nv_bfloat16* __restrict__ Qlo = g_Qlo + (size_t)h * T_SEQ * NFEAT;
    float* __restrict__ Sh = g_S + (size_t)h * T_SEQ * T_SEQ;

    // lower-triangular tile decode
    int lt = blockIdx.x;
    int bi = (int)((sqrtf(8.0f * (float)lt + 1.0f) - 1.0f) * 0.5f);
    while ((bi + 1) * (bi + 2) / 2 <= lt) ++bi;
    while (bi * (bi + 1) / 2 > lt)        --bi;
    const int bj = lt - bi * (bi + 1) / 2;

    const int tid  = threadIdx.x;
    const int lane = tid & 31;
    const int wid  = tid >> 5;
    const int wm   = wid >> 2;   // 0..1
    const int wn   = wid & 3;    // 0..3

    // ---- global-load mapping: 2 uint4 chunks per thread per array ----
    // chunk c in [0,512): row=c>>2, col8=(c&3)*8
    const int c0 = tid, c1 = tid + 256;
    const int r0c = c0 >> 2, k0c = (c0 & 3) * 8;
    const int r1c = c1 >> 2, k1c = (c1 & 3) * 8;
    const __nv_bfloat16* gAhi0 = Qhi + (size_t)(bi * 128 + r0c) * NFEAT + k0c;
    const __nv_bfloat16* gAhi1 = Qhi + (size_t)(bi * 128 + r1c) * NFEAT + k1c;
    const __nv_bfloat16* gAlo0 = Qlo + (size_t)(bi * 128 + r0c) * NFEAT + k0c;
    const __nv_bfloat16* gAlo1 = Qlo + (size_t)(bi * 128 + r1c) * NFEAT + k1c;
    const __nv_bfloat16* gBhi0 = Qhi + (size_t)(bj * 128 + r0c) * NFEAT + k0c;
    const __nv_bfloat16* gBhi1 = Qhi + (size_t)(bj * 128 + r1c) * NFEAT + k1c;
    const __nv_bfloat16* gBlo0 = Qlo + (size_t)(bj * 128 + r0c) * NFEAT + k0c;
    const __nv_bfloat16* gBlo1 = Qlo + (size_t)(bj * 128 + r1c) * NFEAT + k1c;
    const unsigned s0 = (unsigned)(r0c * (LDS_PAD * 2) + k0c * 2);
    const unsigned s1 = (unsigned)(r1c * (LDS_PAD * 2) + k1c * 2);

    // ---- ldmatrix lane offsets ----
    const int g  = lane >> 3;          // matrix id 0..3
    const int rr = lane & 7;
    const int arow = wm * 64 + rr + (g & 1) * 8;     // + mt*16
    const int acol = (g >> 1) * 8;                   // + kk
    unsigned a_off[4];
#pragma unroll
    for (int mt = 0; mt < 4; ++mt)
        a_off[mt] = (unsigned)((arow + mt * 16) * (LDS_PAD * 2) + acol * 2);
    unsigned b_off[2];
#pragma unroll
    for (int np = 0; np < 2; ++np) {
        int brow = wn * 32 + np * 16 + rr + (g & 1) * 8;
        b_off[np] = (unsigned)(brow * (LDS_PAD * 2) + acol * 2);
    }

    float acc[4][4][4];
#pragma unroll
    for (int i = 0; i < 4; ++i)
#pragma unroll
        for (int j = 0; j < 4; ++j)
#pragma unroll
            for (int k = 0; k < 4; ++k) acc[i][j][k] = 0.0f;

    // ---- prologue: load chunk 0 into buffer 0 ----
    {
        uint4 va0 = *(const uint4*)gAhi0, va1 = *(const uint4*)gAhi1;
        uint4 vb0 = *(const uint4*)gAlo0, vb1 = *(const uint4*)gAlo1;
        uint4 vc0 = *(const uint4*)gBhi0, vc1 = *(const uint4*)gBhi1;
        uint4 vd0 = *(const uint4*)gBlo0, vd1 = *(const uint4*)gBlo1;
        *(uint4*)(smem + OFF_AHI + s0) = va0; *(uint4*)(smem + OFF_AHI + s1) = va1;
        *(uint4*)(smem + OFF_ALO + s0) = vb0; *(uint4*)(smem + OFF_ALO + s1) = vb1;
        *(uint4*)(smem + OFF_BHI + s0) = vc0; *(uint4*)(smem + OFF_BHI + s1) = vc1;
        *(uint4*)(smem + OFF_BLO + s0) = vd0; *(uint4*)(smem + OFF_BLO + s1) = vd1;
    }
    __syncthreads();

    const int NKC = NFEAT / BK;   // 256
    unsigned bufb = 0;
    for (int kc = 0; kc < NKC; ++kc) {
        uint4 va0, va1, vb0, vb1, vc0, vc1, vd0, vd1;
        const bool more = (kc + 1 < NKC);
        if (more) {
            size_t o = (size_t)(kc + 1) * BK;
            va0 = *(const uint4*)(gAhi0 + o); va1 = *(const uint4*)(gAhi1 + o);
            vb0 = *(const uint4*)(gAlo0 + o); vb1 = *(const uint4*)(gAlo1 + o);
            vc0 = *(const uint4*)(gBhi0 + o); vc1 = *(const uint4*)(gBhi1 + o);
            vd0 = *(const uint4*)(gBlo0 + o); vd1 = *(const uint4*)(gBlo1 + o);
        }

        const unsigned base = smem_u32 + bufb;
#pragma unroll
        for (int kk = 0; kk < BK; kk += 16) {
            unsigned ahi[4][4], alo[4][4], bhi[4][2], blo[4][2];
#pragma unroll
            for (int mt = 0; mt < 4; ++mt)
                ldsm4(ahi[mt][0], ahi[mt][1], ahi[mt][2], ahi[mt][3],
                      base + OFF_AHI + a_off[mt] + kk * 2);
#pragma unroll
            for (int np = 0; np < 2; ++np) {
                unsigned f0, f1, f2, f3;
                ldsm4(f0, f1, f2, f3, base + OFF_BHI + b_off[np] + kk * 2);
                bhi[2 * np][0] = f0; bhi[2 * np][1] = f2;
                bhi[2 * np + 1][0] = f1; bhi[2 * np + 1][1] = f3;
                ldsm4(f0, f1, f2, f3, base + OFF_BLO + b_off[np] + kk * 2);
                blo[2 * np][0] = f0; blo[2 * np][1] = f2;
                blo[2 * np + 1][0] = f1; blo[2 * np + 1][1] = f3;
            }
#pragma unroll
            for (int mt = 0; mt < 4; ++mt)
                ldsm4(alo[mt][0], alo[mt][1], alo[mt][2], alo[mt][3],
                      base + OFF_ALO + a_off[mt] + kk * 2);

#pragma unroll
            for (int mt = 0; mt < 4; ++mt)
#pragma unroll
                for (int nt = 0; nt < 4; ++nt)
                    mma_bf16(acc[mt][nt], ahi[mt], bhi[nt]);
#pragma unroll
            for (int mt = 0; mt < 4; ++mt)
#pragma unroll
                for (int nt = 0; nt < 4; ++nt)
                    mma_bf16(acc[mt][nt], ahi[mt], blo[nt]);
#pragma unroll
            for (int mt = 0; mt < 4; ++mt)
#pragma unroll
                for (int nt = 0; nt < 4; ++nt)
                    mma_bf16(acc[mt][nt], alo[mt], bhi[nt]);
        }

        if (more) {
            char* nb = smem + (bufb ^ BUF_BYTES);
            *(uint4*)(nb + OFF_AHI + s0) = va0; *(uint4*)(nb + OFF_AHI + s1) = va1;
            *(uint4*)(nb + OFF_ALO + s0) = vb0; *(uint4*)(nb + OFF_ALO + s1) = vb1;
            *(uint4*)(nb + OFF_BHI + s0) = vc0; *(uint4*)(nb + OFF_BHI + s1) = vc1;
            *(uint4*)(nb + OFF_BLO + s0) = vd0; *(uint4*)(nb + OFF_BLO + s1) = vd1;
        }
        __syncthreads();
        bufb ^= BUF_BYTES;
    }

    // ---- writeback with strict-lower mask on diagonal tiles ----
    const bool diag = (bi == bj);
    const int qrow = lane >> 2;           // 0..7
    const int qcol = (lane & 3) * 2;      // 0,2,4,6
#pragma unroll
    for (int mt = 0; mt < 4; ++mt) {
#pragma unroll
        for (int nt = 0; nt < 4; ++nt) {
            int row = bi * 128 + wm * 64 + mt * 16 + qrow;
            int col = bj * 128 + wn * 32 + nt * 8 + qcol;
#pragma unroll
            for (int half = 0; half < 2; ++half) {     // m, m+8
                int r = row + half * 8;
                float v0 = acc[mt][nt][half * 2 + 0];
                float v1 = acc[mt][nt][half * 2 + 1];
                if (diag) {
                    if (col + 0 >= r) v0 = 0.0f;
                    if (col + 1 >= r) v1 = 0.0f;
                }
                *(float2*)(Sh + (size_t)r * T_SEQ + col) = make_float2(v0, v1);
            }
        }
    }
}

// ============================================================================
// Kernel 4: out = S * V per head, reading only tiles kt <= bi (fp32 SIMT).
// ============================================================================
__global__ __launch_bounds__(256, 2) void gemm_out_kernel(const float* __restrict__ V,
                                                          float* __restrict__ O) {
    const int h  = blockIdx.z;
    const int bi = blockIdx.y;
    const int bj = blockIdx.x;
    const float* __restrict__ Sh = g_S + (size_t)h * T_SEQ * T_SEQ;
    float* __restrict__ Oh = O + (size_t)h * T_SEQ * DV;

    __shared__ float As[2][8][132];
    __shared__ float Bs[2][8][132];

    const int tid  = threadIdx.x;
    const int lrow = tid >> 1;
    const int c4   = (tid & 1) * 4;
    const float* ga = Sh + (size_t)(bi * 128 + lrow) * T_SEQ + c4;

    const int vrow = tid >> 5;
    const int vcol = (tid & 31) * 4;
    const float* gv = V + (size_t)vrow * DV + bj * 128 + vcol;

    const int tx = tid & 15, ty = tid >> 4;

    float acc[8][8];
#pragma unroll
    for (int i = 0; i < 8; ++i)
#pragma unroll
        for (int j = 0; j < 8; ++j) acc[i][j] = 0.0f;

    {
        float4 ra = *(const float4*)ga;
        float4 rv = *(const float4*)gv;
        As[0][c4 + 0][lrow] = ra.x; As[0][c4 + 1][lrow] = ra.y;
        As[0][c4 + 2][lrow] = ra.z; As[0][c4 + 3][lrow] = ra.w;
        *(float4*)&Bs[0][vrow][vcol] = rv;
    }
    __syncthreads();

    const int NK = (bi + 1) * 16;
    int buf = 0;
    for (int kc = 0; kc < NK; ++kc) {
        float4 na, nv;
        if (kc + 1 < NK) {
            na = *(const float4*)(ga + (size_t)(kc + 1) * 8);
            nv = *(const float4*)(gv + (size_t)(kc + 1) * 8 * DV);
        }
#pragma unroll
        for (int k = 0; k < 8; ++k) {
            float4 a0 = *(const float4*)&As[buf][k][ty * 8];
            float4 a1 = *(const float4*)&As[buf][k][ty * 8 + 4];
            float4 b0 = *(const float4*)&Bs[buf][k][tx * 8];
            float4 b1 = *(const float4*)&Bs[buf][k][tx * 8 + 4];
            float a[8] = {a0.x, a0.y, a0.z, a0.w, a1.x, a1.y, a1.z, a1.w};
            float b[8] = {b0.x, b0.y, b0.z, b0.w, b1.x, b1.y, b1.z, b1.w};
#pragma unroll
            for (int i = 0; i < 8; ++i)
#pragma unroll
                for (int j = 0; j < 8; ++j)
                    acc[i][j] = fmaf(a[i], b[j], acc[i][j]);
        }
        if (kc + 1 < NK) {
            int nb2 = buf ^ 1;
            As[nb2][c4 + 0][lrow] = na.x; As[nb2][c4 + 1][lrow] = na.y;
            As[nb2][c4 + 2][lrow] = na.z; As[nb2][c4 + 3][lrow] = na.w;
            *(float4*)&Bs[nb2][vrow][vcol] = nv;
        }
        __syncthreads();
        buf ^= 1;
    }

    const int row0 = bi * 128 + ty * 8;
    const int col0 = bj * 128 + tx * 8;
#pragma unroll
    for (int i = 0; i < 8; ++i) {
        float* dst = Oh + (size_t)(row0 + i) * DV + col0;
        *(float4*)(dst)     = make_float4(acc[i][0], acc[i][1], acc[i][2], acc[i][3]);
        *(float4*)(dst + 4) = make_float4(acc[i][4], acc[i][5], acc[i][6], acc[i][7]);
    }
}

// ============================================================================
extern "C" void kernel_launch(void* const* d_in, const int* in_sizes, int n_in,
                              void* d_out, int out_size) {
    const float* Q = (const float*)d_in[0];
    const float* V = (const float*)d_in[1];
    float* O = (float*)d_out;

    static bool attr_set = false;
    if (!attr_set) {
        cudaFuncSetAttribute(gemm_scores_kernel,
                             cudaFuncAttributeMaxDynamicSharedMemorySize, SMEM_BYTES);
        attr_set = true;
    }

    const int tab_elems  = T_SEQ * HALF_N;
    const int rope_pairs = NH * T_SEQ * HALF_N;

    freq_kernel<<<(HALF_N + 255) / 256, 256>>>();
    build_tab_kernel<<<(tab_elems + 255) / 256, 256>>>();
    rope_kernel<<<(rope_pairs + 255) / 256, 256>>>(Q);
    gemm_scores_kernel<<<dim3(136, NH), 256, SMEM_BYTES>>>();
    gemm_out_kernel<<<dim3(DV / 128, T_SEQ / 128, NH), 256>>>(V, O);
}